// round 2
// baseline (speedup 1.0000x reference)
#include <cuda_runtime.h>
#include <cuda_bf16.h>
#include <math.h>

// Problem constants (from reference)
#define N_IN   100000
#define N_OUT  200000
#define C_IN   128
#define C_OUT  64
#define KOFF   27
#define MPAIRS 100000
#define BN_EPS 1e-5f

// Conv kernel tiling
#define WARPS_PER_BLOCK 8
#define PPW 8                               // pairs processed simultaneously per warp
#define PAIRS_PER_CHUNK (WARPS_PER_BLOCK * PPW)   // 64
#define NCHUNKS ((MPAIRS + PAIRS_PER_CHUNK - 1) / PAIRS_PER_CHUNK)  // 1563
#define CONV_GRID_X 118

// BN stats scratch (no cudaMalloc allowed -> __device__ globals)
__device__ float g_sum[C_OUT];
__device__ float g_sq[C_OUT];
__device__ float g_scale[C_OUT];
__device__ float g_bias[C_OUT];

// ---------------------------------------------------------------------------
// Kernel 1: gather -> per-k GEMM -> scatter-add (atomic) into out
// Block: 256 threads (8 warps). blockIdx.y = kernel offset k.
// SMEM: [0, 8192) floats: weight[k] (128x64)
//       [8192, 16384) floats: x staging, 8 warps x 8 pairs x 128 ch
// ---------------------------------------------------------------------------
__global__ void __launch_bounds__(256, 3) conv_kernel(
    const float* __restrict__ x,
    const float* __restrict__ weight,
    const int*   __restrict__ in_map,
    const int*   __restrict__ out_map,
    float*       __restrict__ out)
{
    extern __shared__ float smem[];
    float* wsh = smem;                       // 128*64 floats = 32KB
    float* xsh = smem + C_IN * C_OUT;        // 8*8*128 floats = 32KB

    const int k = blockIdx.y;

    // Load weight[k] into shared (vectorized)
    {
        const float4* src = (const float4*)(weight + (size_t)k * C_IN * C_OUT);
        float4* dst = (float4*)wsh;
        #pragma unroll 4
        for (int i = threadIdx.x; i < C_IN * C_OUT / 4; i += blockDim.x)
            dst[i] = src[i];
    }
    __syncthreads();

    const int warp = threadIdx.x >> 5;
    const int lane = threadIdx.x & 31;
    float* xw = xsh + warp * (PPW * C_IN);   // this warp's staging region

    for (int chunk = blockIdx.x; chunk < NCHUNKS; chunk += gridDim.x) {
        const int base = chunk * PAIRS_PER_CHUNK + warp * PPW;

        // Gather 8 x-rows into shared; each lane loads one float4 per row.
        int orow[PPW];
        #pragma unroll
        for (int p = 0; p < PPW; p++) {
            const int idx = base + p;
            if (idx < MPAIRS) {
                const int gi = k * MPAIRS + idx;
                const int ir = in_map[gi];
                orow[p] = out_map[gi];
                float4 v = ((const float4*)(x + (size_t)ir * C_IN))[lane];
                ((float4*)(xw + p * C_IN))[lane] = v;
            } else {
                orow[p] = -1;
            }
        }
        __syncwarp();

        // Each lane owns output channels (2*lane, 2*lane+1) for all 8 pairs.
        float2 acc[PPW];
        #pragma unroll
        for (int p = 0; p < PPW; p++) acc[p] = make_float2(0.f, 0.f);

        #pragma unroll
        for (int c4 = 0; c4 < C_IN / 4; c4++) {
            // weight rows c4*4 .. c4*4+3, channels (2*lane, 2*lane+1)
            float2 w0 = *(const float2*)&wsh[(c4 * 4 + 0) * C_OUT + 2 * lane];
            float2 w1 = *(const float2*)&wsh[(c4 * 4 + 1) * C_OUT + 2 * lane];
            float2 w2 = *(const float2*)&wsh[(c4 * 4 + 2) * C_OUT + 2 * lane];
            float2 w3 = *(const float2*)&wsh[(c4 * 4 + 3) * C_OUT + 2 * lane];
            #pragma unroll
            for (int p = 0; p < PPW; p++) {
                float4 xv = ((const float4*)(xw + p * C_IN))[c4];  // broadcast
                acc[p].x = fmaf(xv.x, w0.x, acc[p].x);
                acc[p].y = fmaf(xv.x, w0.y, acc[p].y);
                acc[p].x = fmaf(xv.y, w1.x, acc[p].x);
                acc[p].y = fmaf(xv.y, w1.y, acc[p].y);
                acc[p].x = fmaf(xv.z, w2.x, acc[p].x);
                acc[p].y = fmaf(xv.z, w2.y, acc[p].y);
                acc[p].x = fmaf(xv.w, w3.x, acc[p].x);
                acc[p].y = fmaf(xv.w, w3.y, acc[p].y);
            }
        }

        // Scatter-add: per pair, the warp writes 64 consecutive floats (256B)
        // via vector reduction atomics (coalesced at L2).
        #pragma unroll
        for (int p = 0; p < PPW; p++) {
            if (orow[p] >= 0) {
                float* dst = out + (size_t)orow[p] * C_OUT + 2 * lane;
                asm volatile("red.global.add.v2.f32 [%0], {%1, %2};"
                             :: "l"(dst), "f"(acc[p].x), "f"(acc[p].y) : "memory");
            }
        }
        __syncwarp();   // protect xsh before next chunk's gather overwrites it
    }
}

// ---------------------------------------------------------------------------
// Kernel 2a: zero stats accumulators
// ---------------------------------------------------------------------------
__global__ void zero_stats_kernel() {
    if (threadIdx.x < C_OUT) { g_sum[threadIdx.x] = 0.f; g_sq[threadIdx.x] = 0.f; }
}

// ---------------------------------------------------------------------------
// Kernel 2b: per-channel sum / sumsq over [N_OUT, 64]
// 256 threads = 4 rows x 64 channels per step (coalesced 256B per row).
// ---------------------------------------------------------------------------
__global__ void stats_kernel(const float* __restrict__ out) {
    const int c    = threadIdx.x & 63;
    const int rsub = threadIdx.x >> 6;   // 0..3
    float s = 0.f, q = 0.f;
    for (int r = blockIdx.x * 4 + rsub; r < N_OUT; r += gridDim.x * 4) {
        float v = out[(size_t)r * C_OUT + c];
        s += v;
        q = fmaf(v, v, q);
    }
    __shared__ float ssh[256];
    __shared__ float qsh[256];
    ssh[threadIdx.x] = s;
    qsh[threadIdx.x] = q;
    __syncthreads();
    if (rsub == 0) {
        s = ssh[c] + ssh[c + 64] + ssh[c + 128] + ssh[c + 192];
        q = qsh[c] + qsh[c + 64] + qsh[c + 128] + qsh[c + 192];
        atomicAdd(&g_sum[c], s);
        atomicAdd(&g_sq[c], q);
    }
}

// ---------------------------------------------------------------------------
// Kernel 3: finalize BN affine params
// ---------------------------------------------------------------------------
__global__ void finalize_kernel(const float* __restrict__ gamma,
                                const float* __restrict__ beta) {
    const int c = threadIdx.x;
    if (c < C_OUT) {
        const float invn = 1.0f / (float)N_OUT;
        float mean = g_sum[c] * invn;
        float var  = g_sq[c] * invn - mean * mean;
        float sc   = gamma[c] * rsqrtf(var + BN_EPS);
        g_scale[c] = sc;
        g_bias[c]  = beta[c] - mean * sc;
    }
}

// ---------------------------------------------------------------------------
// Kernel 4: in-place normalize + ReLU, vectorized float4
// ---------------------------------------------------------------------------
__global__ void norm_kernel(float* __restrict__ out, long long n4) {
    long long i = (long long)blockIdx.x * blockDim.x + threadIdx.x;
    if (i < n4) {
        float4 v = ((float4*)out)[i];
        int c0 = (int)((i * 4) & 63);
        v.x = fmaxf(fmaf(v.x, g_scale[c0 + 0], g_bias[c0 + 0]), 0.f);
        v.y = fmaxf(fmaf(v.y, g_scale[c0 + 1], g_bias[c0 + 1]), 0.f);
        v.z = fmaxf(fmaf(v.z, g_scale[c0 + 2], g_bias[c0 + 2]), 0.f);
        v.w = fmaxf(fmaf(v.w, g_scale[c0 + 3], g_bias[c0 + 3]), 0.f);
        ((float4*)out)[i] = v;
    }
}

// ---------------------------------------------------------------------------
// kernel_launch — graph-capturable pipeline, default stream
// Inputs (metadata order): x, weight, gamma, beta, in_map, out_map
// ---------------------------------------------------------------------------
extern "C" void kernel_launch(void* const* d_in, const int* in_sizes, int n_in,
                              void* d_out, int out_size)
{
    const float* x       = (const float*)d_in[0];
    const float* weight  = (const float*)d_in[1];
    const float* gamma   = (const float*)d_in[2];
    const float* beta    = (const float*)d_in[3];
    const int*   in_map  = (const int*)d_in[4];
    const int*   out_map = (const int*)d_in[5];
    float*       out     = (float*)d_out;

    // Conv accumulates into d_out; it is poisoned, so zero it first.
    cudaMemsetAsync(out, 0, (size_t)out_size * sizeof(float));
    zero_stats_kernel<<<1, 64>>>();

    // 64KB dynamic shared -> opt in above the 48KB static limit.
    const int smem_bytes = (C_IN * C_OUT + WARPS_PER_BLOCK * PPW * C_IN) * (int)sizeof(float);
    cudaFuncSetAttribute(conv_kernel, cudaFuncAttributeMaxDynamicSharedMemorySize, smem_bytes);

    dim3 cgrid(CONV_GRID_X, KOFF);
    conv_kernel<<<cgrid, 256, smem_bytes>>>(x, weight, in_map, out_map, out);

    stats_kernel<<<592, 256>>>(out);
    finalize_kernel<<<1, 64>>>(gamma, beta);

    long long n4 = (long long)out_size / 4;
    norm_kernel<<<(int)((n4 + 255) / 256), 256>>>(out, n4);
}